// round 13
// baseline (speedup 1.0000x reference)
#include <cuda_runtime.h>
#include <cuda_bf16.h>
#include <math.h>
#include <stdint.h>

// ---------------------------------------------------------------- constants
#define NSEQ      400
#define NSEG      50
#define SEGLEN    4
#define C         64
#define TT        200
#define VV        25
#define HID       128
#define GATES     512
#define LEVY      2016
#define LSDIM     2144
#define MROWS     20000
#define MPAD      20096        // 157*128
#define KPAD      2176         // 68*32
#define KSTAGES   68           // K stages of 32 int8 elems
#define INV254    (1.0f / 254.0f)

// ---------------------------------------------------------------- scratch
__device__ int8_t g_Ahi[(size_t)MPAD * KPAD];    // logsig features, digit hi
__device__ int8_t g_Alo[(size_t)MPAD * KPAD];    // digit lo
__device__ int8_t g_Bhi[(size_t)GATES * KPAD];   // W_ih digit hi
__device__ int8_t g_Blo[(size_t)GATES * KPAD];   // W_ih digit lo
__device__ float  g_sA[MPAD];                    // per-row scale of A
__device__ float  g_sB[GATES];                   // per-row scale of B
__device__ float  g_xproj[(size_t)MROWS * GATES];
__device__ float  g_WhhT[HID * GATES];
__device__ float  g_bias[GATES];

__device__ __forceinline__ float ex2f(float x) {
    float y; asm("ex2.approx.f32 %0, %1;" : "=f"(y) : "f"(x)); return y;
}
__device__ __forceinline__ float rcpf(float x) {
    float y; asm("rcp.approx.f32 %0, %1;" : "=f"(y) : "f"(x)); return y;
}
__device__ __forceinline__ float fast_sigmoid(float x) {
    return rcpf(1.0f + ex2f(-1.4426950408889634f * x));
}
__device__ __forceinline__ float fast_tanh(float x) {
    return 2.0f * rcpf(1.0f + ex2f(-2.8853900817779268f * x)) - 1.0f;
}

__device__ __forceinline__ uint32_t smem_u32(const void* p) {
    uint32_t a;
    asm("{ .reg .u64 t; cvta.to.shared.u64 t, %1; cvt.u32.u64 %0, t; }" : "=r"(a) : "l"(p));
    return a;
}

static __device__ __forceinline__ void cp16(uint32_t s, const void* g) {
    asm volatile("cp.async.cg.shared.global [%0], [%1], 16;\n" :: "r"(s), "l"(g));
}
#define CP_COMMIT()  asm volatile("cp.async.commit_group;\n" ::: "memory")
#define CP_WAIT0()   asm volatile("cp.async.wait_group 0;\n" ::: "memory")

static __device__ __forceinline__ void ldsm4(uint32_t* r, uint32_t addr) {
    asm volatile("ldmatrix.sync.aligned.m8n8.x4.shared.b16 {%0,%1,%2,%3}, [%4];\n"
                 : "=r"(r[0]), "=r"(r[1]), "=r"(r[2]), "=r"(r[3]) : "r"(addr));
}

// s8 x s8 -> s32, K=32.  Same fragment geometry as bf16 k16 via b16-view ldmatrix.
static __device__ __forceinline__ void mma_s8(int* c, const uint32_t* a,
                                              const uint32_t* b) {
    asm volatile(
        "mma.sync.aligned.m16n8k32.row.col.s32.s8.s8.s32 "
        "{%0,%1,%2,%3}, {%4,%5,%6,%7}, {%8,%9}, {%0,%1,%2,%3};\n"
        : "+r"(c[0]), "+r"(c[1]), "+r"(c[2]), "+r"(c[3])
        : "r"(a[0]), "r"(a[1]), "r"(a[2]), "r"(a[3]), "r"(b[0]), "r"(b[1]));
}

// quantize one value given scale s and inv = 127/smax: hi + lo/254 digits
static __device__ __forceinline__ void quant2(float val, float s, float inv,
                                              int8_t* hi, int8_t* lo) {
    float fh = rintf(val * inv);
    fh = fminf(fmaxf(fh, -127.0f), 127.0f);
    float r = val - fh * s;
    float fl = rintf(r * inv * 254.0f);
    fl = fminf(fmaxf(fl, -127.0f), 127.0f);
    *hi = (int8_t)(int)fh;
    *lo = (int8_t)(int)fl;
}

// ---------------------------------------------------------------- prep
__global__ void prep_kernel(const float* __restrict__ Whh,
                            const float* __restrict__ bih,
                            const float* __restrict__ bhh) {
    int g = blockIdx.x * blockDim.x + threadIdx.x;
    if (g < GATES) {
        g_bias[g] = bih[g] + bhh[g];
        for (int k = 0; k < HID; k++)
            g_WhhT[k * GATES + g] = Whh[g * HID + k];
    }
}

// W_ih row -> int8 hi/lo with per-row scale.  One block per gate row.
__global__ __launch_bounds__(256) void wprep_kernel(const float* __restrict__ Wih) {
    const int row = blockIdx.x;   // 0..511
    const int tid = threadIdx.x;
    __shared__ float red[256];

    float lmax = 0.0f;
    for (int col = tid; col < LSDIM; col += 256)
        lmax = fmaxf(lmax, fabsf(Wih[(size_t)row * LSDIM + col]));
    red[tid] = lmax;
    __syncthreads();
    for (int off = 128; off; off >>= 1) {
        if (tid < off) red[tid] = fmaxf(red[tid], red[tid + off]);
        __syncthreads();
    }
    const float smax = fmaxf(red[0], 1e-20f);
    const float s = smax * (1.0f / 127.0f);
    const float inv = 127.0f / smax;

    for (int col = tid; col < LSDIM; col += 256) {
        float v = Wih[(size_t)row * LSDIM + col];
        int8_t hi, lo;
        quant2(v, s, inv, &hi, &lo);
        g_Bhi[(size_t)row * KPAD + col] = hi;
        g_Blo[(size_t)row * KPAD + col] = lo;
    }
    if (tid == 0) g_sB[row] = s;
}

// ---------------------------------------------------------------- K1: logsig
#define PSTRIDE 101

__global__ __launch_bounds__(256) void logsig_kernel(const float* __restrict__ x) {
    const int bs = blockIdx.x;           // 0..799
    const int b = bs / NSEG, s = bs % NSEG;
    const int tid = threadIdx.x;

    __shared__ float p[C][PSTRIDE];      // p[c][t*25+v]
    __shared__ uint8_t s_iu[LEVY], s_ju[LEVY];
    __shared__ float sfeat[LSDIM];
    __shared__ float red[256];

    for (int idx = tid; idx < C * (SEGLEN * VV); idx += 256) {
        int c = idx / (SEGLEN * VV);
        int r = idx % (SEGLEN * VV);     // r = t*VV + v
        p[c][r] = x[(((size_t)b * C + c) * TT + s * SEGLEN) * VV + r];
    }
    for (int k = tid; k < LEVY; k += 256) {
        int i = 0, rem = k;
        while (rem >= (C - 1 - i)) { rem -= (C - 1 - i); i++; }
        s_iu[k] = (uint8_t)i;
        s_ju[k] = (uint8_t)(i + 1 + rem);
    }
    __syncthreads();

    for (int v = 0; v < VV; v++) {
        const size_t row = ((size_t)(b * VV + v) * NSEG + s);

        // pass 1: compute features, track block max
        float lmax = 0.0f;
        for (int k = tid; k < LSDIM; k += 256) {
            float val;
            if (k < C) {
                val = p[k][3 * VV + v] - p[k][v];
            } else if (k < C + LEVY) {
                int i = s_iu[k - C], j = s_ju[k - C];
                float si = p[i][v], sj = p[j][v];
                float a = 0.0f;
#pragma unroll
                for (int t = 0; t < SEGLEN - 1; t++) {
                    float pit = p[i][t * VV + v], pjt = p[j][t * VV + v];
                    float devi = pit - si;
                    float devj = pjt - sj;
                    float inci = p[i][(t + 1) * VV + v] - pit;
                    float incj = p[j][(t + 1) * VV + v] - pjt;
                    a += devi * incj - devj * inci;
                }
                val = 0.5f * a;
            } else {
                val = p[k - C - LEVY][v];
            }
            sfeat[k] = val;
            lmax = fmaxf(lmax, fabsf(val));
        }
        red[tid] = lmax;
        __syncthreads();
        for (int off = 128; off; off >>= 1) {
            if (tid < off) red[tid] = fmaxf(red[tid], red[tid + off]);
            __syncthreads();
        }
        const float smax = fmaxf(red[0], 1e-20f);
        const float sc = smax * (1.0f / 127.0f);
        const float inv = 127.0f / smax;

        // pass 2: quantize and store
        int8_t* ohi = g_Ahi + row * KPAD;
        int8_t* olo = g_Alo + row * KPAD;
        for (int k = tid; k < LSDIM; k += 256) {
            int8_t hi, lo;
            quant2(sfeat[k], sc, inv, &hi, &lo);
            ohi[k] = hi;
            olo[k] = lo;
        }
        if (tid == 0) g_sA[row] = sc;
        __syncthreads();    // protect sfeat/red for next v
    }
}

// ---------------------------------------------------------------- K2: s8 IMMA GEMM
// CTA tile M=128 x N=64, BK=32 int8, 8 warps (warp tile 32x32), 2-stage cp.async.
// I1 += Ahi*Bhi ; I2 += Ahi*Blo + Alo*Bhi  (exact s32 accumulation)
// out = sA*sB*(I1 + I2/254) + bias
// SROWB=48: multiple of 16 so every ldmatrix per-lane row address is 16B-aligned.
#define SROWB     48                  // smem row stride bytes (32 data + 16 pad)
#define A_BYTES   (128 * SROWB)       // 6144 B per A array
#define B_BYTES   (64  * SROWB)       // 3072 B per B array
#define OFF_AHI   0
#define OFF_ALO   (A_BYTES)
#define OFF_BHI   (2 * A_BYTES)
#define OFF_BLO   (2 * A_BYTES + B_BYTES)
#define STG       (2 * A_BYTES + 2 * B_BYTES)   // 18432 B per stage
#define NSTAGE    2
#define GEMM_SMEM (NSTAGE * STG)      // 36864 B

extern __shared__ char dynsm[];

static __device__ __forceinline__ void load_stage(int tid, int bm, int bn, int s,
                                                  uint32_t sbase) {
    const size_t kb = (size_t)s * 32;    // byte offset within an int8 row
    {   // A: 128 rows x 2 chunks(16B) per array
        int row = tid >> 1, c = tid & 1;
        uint32_t dst = (uint32_t)(row * SROWB + c * 16);
        size_t gA = (size_t)(bm + row) * KPAD + kb + c * 16;
        cp16(sbase + OFF_AHI + dst, g_Ahi + gA);
        cp16(sbase + OFF_ALO + dst, g_Alo + gA);
    }
    {   // B: 64 rows x 2 chunks per array; split across thread halves
        int t = tid & 127;
        int row = t >> 1, c = t & 1;
        uint32_t dst = (uint32_t)(row * SROWB + c * 16);
        size_t gB = (size_t)(bn + row) * KPAD + kb + c * 16;
        if (tid < 128) cp16(sbase + OFF_BHI + dst, g_Bhi + gB);
        else           cp16(sbase + OFF_BLO + dst, g_Blo + gB);
    }
    CP_COMMIT();
}

__global__ __launch_bounds__(256, 2) void gemm_mma_kernel() {
    __shared__ float s_bias[64];
    __shared__ float s_sb[64];

    const int tid  = threadIdx.x;
    const int bn   = blockIdx.x * 64;    // N fastest: consecutive CTAs share A tile
    const int bm   = blockIdx.y * 128;
    const int lane = tid & 31;
    const int wid  = tid >> 5;
    const int wm   = (wid & 3) * 32;     // warp M origin: 0,32,64,96
    const int wn   = (wid >> 2) * 32;    // warp N origin: 0,32

    const uint32_t sbase = smem_u32(dynsm);

    if (tid < 64) {
        s_bias[tid] = g_bias[bn + tid];
        s_sb[tid]   = g_sB[bn + tid];
    }

    // ldmatrix per-lane address components (b16-view of int8 data)
    const int rowA = wm + (lane & 7) + (((lane >> 3) & 1) << 3);
    const int colA = (((lane >> 4) & 1) << 4);   // byte offset: 0 or 16
    const int rowB = wn + (lane & 7) + (((lane >> 4) & 1) << 3);
    const int colB = (((lane >> 3) & 1) << 4);   // byte offset: 0 or 16

    int acc1[2][4][4], acc2[2][4][4];
#pragma unroll
    for (int f = 0; f < 2; f++)
#pragma unroll
        for (int n = 0; n < 4; n++)
#pragma unroll
            for (int q = 0; q < 4; q++) { acc1[f][n][q] = 0; acc2[f][n][q] = 0; }

    // prologue: stage 0
    load_stage(tid, bm, bn, 0, sbase);

    for (int s = 0; s < KSTAGES; s++) {
        CP_WAIT0();          // stage s resident
        __syncthreads();

        if (s + 1 < KSTAGES) // prefetch next stage into the other buffer
            load_stage(tid, bm, bn, s + 1, sbase + (uint32_t)((s + 1) & 1) * STG);

        const uint32_t buf = sbase + (uint32_t)(s & 1) * STG;

        uint32_t ah[2][4], al[2][4], bh[2][4], bl[2][4];
#pragma unroll
        for (int p = 0; p < 2; p++) {
            uint32_t off = (uint32_t)((rowB + 16 * p) * SROWB + colB);
            ldsm4(bh[p], buf + OFF_BHI + off);
            ldsm4(bl[p], buf + OFF_BLO + off);
        }
#pragma unroll
        for (int f = 0; f < 2; f++) {
            uint32_t off = (uint32_t)((rowA + 16 * f) * SROWB + colA);
            ldsm4(ah[f], buf + OFF_AHI + off);
            ldsm4(al[f], buf + OFF_ALO + off);
        }
#pragma unroll
        for (int f = 0; f < 2; f++)
#pragma unroll
            for (int n = 0; n < 4; n++) {
                const uint32_t* Bh = &bh[n >> 1][(n & 1) * 2];
                const uint32_t* Bl = &bl[n >> 1][(n & 1) * 2];
                mma_s8(acc1[f][n], ah[f], Bh);
                mma_s8(acc2[f][n], ah[f], Bl);
                mma_s8(acc2[f][n], al[f], Bh);
            }
    }

    // epilogue
    const int r0base = bm + wm + (lane >> 2);
    const int cloc   = wn + 2 * (lane & 3);
#pragma unroll
    for (int f = 0; f < 2; f++) {
        int r0 = r0base + f * 16;
        int r1 = r0 + 8;
        float sa0 = g_sA[r0];
        float sa1 = g_sA[r1];
#pragma unroll
        for (int n = 0; n < 4; n++) {
            int cl = cloc + n * 8;
            float sb0 = s_sb[cl], sb1 = s_sb[cl + 1];
            if (r0 < MROWS) {
                float2 v;
                v.x = sa0 * sb0 * ((float)acc1[f][n][0] + (float)acc2[f][n][0] * INV254)
                      + s_bias[cl];
                v.y = sa0 * sb1 * ((float)acc1[f][n][1] + (float)acc2[f][n][1] * INV254)
                      + s_bias[cl + 1];
                *(float2*)&g_xproj[(size_t)r0 * GATES + bn + cl] = v;
            }
            if (r1 < MROWS) {
                float2 v;
                v.x = sa1 * sb0 * ((float)acc1[f][n][2] + (float)acc2[f][n][2] * INV254)
                      + s_bias[cl];
                v.y = sa1 * sb1 * ((float)acc1[f][n][3] + (float)acc2[f][n][3] * INV254)
                      + s_bias[cl + 1];
                *(float2*)&g_xproj[(size_t)r1 * GATES + bn + cl] = v;
            }
        }
    }
}

// ---------------------------------------------------------------- K3: LSTM
#define REGK 96
#define TAILK 32
#define LSTM_SMEM (TAILK * GATES * 4)

__global__ __launch_bounds__(512, 1) void lstm_kernel(float* __restrict__ out) {
    const int g = threadIdx.x;
    const int n0 = blockIdx.x * 4;

    __shared__ float4 hs[HID];
    __shared__ float  cs[4][HID];
    __shared__ float  gsm[4][GATES];
    float* sWtail = (float*)dynsm;   // [TAILK][GATES]

    float w[REGK];
#pragma unroll
    for (int k = 0; k < REGK; k++) w[k] = g_WhhT[k * GATES + g];
#pragma unroll
    for (int kk = 0; kk < TAILK; kk++)
        sWtail[kk * GATES + g] = g_WhhT[(REGK + kk) * GATES + g];

    if (g < HID) {
        hs[g] = make_float4(0.f, 0.f, 0.f, 0.f);
        cs[0][g] = 0.f; cs[1][g] = 0.f; cs[2][g] = 0.f; cs[3][g] = 0.f;
    }
    __syncthreads();

    const float* xp = g_xproj + (size_t)n0 * NSEG * GATES + g;

    const int m_  = g >> 7;
    const int hid = g & 127;
    const int n   = n0 + m_;
    const int b   = n / VV;
    const int v   = n % VV;
    float* outp = out + ((size_t)(b * HID + hid) * NSEG) * VV + v;

    for (int s = 0; s < NSEG; s++) {
        float a0 = xp[(0 * NSEG + s) * GATES];
        float a1 = xp[(1 * NSEG + s) * GATES];
        float a2 = xp[(2 * NSEG + s) * GATES];
        float a3 = xp[(3 * NSEG + s) * GATES];
#pragma unroll
        for (int k = 0; k < REGK; k++) {
            float4 h4 = hs[k];
            float wk = w[k];
            a0 += h4.x * wk; a1 += h4.y * wk; a2 += h4.z * wk; a3 += h4.w * wk;
        }
#pragma unroll
        for (int kk = 0; kk < TAILK; kk++) {
            float4 h4 = hs[REGK + kk];
            float wk = sWtail[kk * GATES + g];
            a0 += h4.x * wk; a1 += h4.y * wk; a2 += h4.z * wk; a3 += h4.w * wk;
        }
        gsm[0][g] = a0; gsm[1][g] = a1; gsm[2][g] = a2; gsm[3][g] = a3;
        __syncthreads();

        {
            float gi = gsm[m_][hid];
            float gf = gsm[m_][HID + hid];
            float gg = gsm[m_][2 * HID + hid];
            float go = gsm[m_][3 * HID + hid];
            float c  = cs[m_][hid];
            float cn = fast_sigmoid(gf) * c + fast_sigmoid(gi) * fast_tanh(gg);
            float h  = fast_sigmoid(go) * fast_tanh(cn);
            cs[m_][hid] = cn;
            ((float*)&hs[hid])[m_] = h;
            outp[s * VV] = h;
        }
        __syncthreads();
    }
}

// ---------------------------------------------------------------- launch
extern "C" void kernel_launch(void* const* d_in, const int* in_sizes, int n_in,
                              void* d_out, int out_size) {
    const float* x   = (const float*)d_in[0];
    const float* Wih = (const float*)d_in[1];
    const float* Whh = (const float*)d_in[2];
    const float* bih = (const float*)d_in[3];
    const float* bhh = (const float*)d_in[4];
    float* out = (float*)d_out;

    cudaFuncSetAttribute(gemm_mma_kernel,
                         cudaFuncAttributeMaxDynamicSharedMemorySize, GEMM_SMEM);
    cudaFuncSetAttribute(lstm_kernel,
                         cudaFuncAttributeMaxDynamicSharedMemorySize, LSTM_SMEM);

    prep_kernel<<<2, 256>>>(Whh, bih, bhh);
    wprep_kernel<<<GATES, 256>>>(Wih);
    logsig_kernel<<<16 * NSEG, 256>>>(x);
    dim3 grid(GATES / 64, MPAD / 128);   // (8, 157), N fastest
    gemm_mma_kernel<<<grid, 256, GEMM_SMEM>>>();
    lstm_kernel<<<NSEQ / 4, 512, LSTM_SMEM>>>(out);
}

// round 14
// speedup vs baseline: 2.3282x; 2.3282x over previous
#include <cuda_runtime.h>
#include <cuda_fp16.h>
#include <math.h>
#include <stdint.h>

// ---------------------------------------------------------------- constants
#define NSEQ      400
#define NSEG      50
#define SEGLEN    4
#define C         64
#define TT        200
#define VV        25
#define HID       128
#define GATES     512
#define LEVY      2016
#define LSDIM     2144
#define MROWS     20000
#define MPAD      20096        // 157*128
#define KPAD      2176         // 68*32
#define KSTAGES   68           // K stages of 32 fp16 elems
#define ROWB      (KPAD*2)     // bytes per fp16 row

// ---------------------------------------------------------------- scratch
__device__ __half g_A  [(size_t)MPAD * KPAD];    // logsig features (fp16)
__device__ __half g_Bhi[(size_t)GATES * KPAD];   // W_ih hi digit
__device__ __half g_Blo[(size_t)GATES * KPAD];   // W_ih lo digit
__device__ float  g_xproj[(size_t)MROWS * GATES];
__device__ float  g_WhhT[HID * GATES];
__device__ float  g_bias[GATES];

__device__ __forceinline__ float ex2f(float x) {
    float y; asm("ex2.approx.f32 %0, %1;" : "=f"(y) : "f"(x)); return y;
}
__device__ __forceinline__ float rcpf(float x) {
    float y; asm("rcp.approx.f32 %0, %1;" : "=f"(y) : "f"(x)); return y;
}
__device__ __forceinline__ float fast_sigmoid(float x) {
    return rcpf(1.0f + ex2f(-1.4426950408889634f * x));
}
__device__ __forceinline__ float fast_tanh(float x) {
    return 2.0f * rcpf(1.0f + ex2f(-2.8853900817779268f * x)) - 1.0f;
}

__device__ __forceinline__ uint32_t smem_u32(const void* p) {
    uint32_t a;
    asm("{ .reg .u64 t; cvta.to.shared.u64 t, %1; cvt.u32.u64 %0, t; }" : "=r"(a) : "l"(p));
    return a;
}

static __device__ __forceinline__ void cp16(uint32_t s, const void* g) {
    asm volatile("cp.async.cg.shared.global [%0], [%1], 16;\n" :: "r"(s), "l"(g));
}
#define CP_COMMIT()  asm volatile("cp.async.commit_group;\n" ::: "memory")
#define CP_WAIT0()   asm volatile("cp.async.wait_group 0;\n" ::: "memory")

static __device__ __forceinline__ void ldsm4(uint32_t* r, uint32_t addr) {
    asm volatile("ldmatrix.sync.aligned.m8n8.x4.shared.b16 {%0,%1,%2,%3}, [%4];\n"
                 : "=r"(r[0]), "=r"(r[1]), "=r"(r[2]), "=r"(r[3]) : "r"(addr));
}

static __device__ __forceinline__ void mma16816(float* c, const uint32_t* a,
                                                const uint32_t* b) {
    asm volatile(
        "mma.sync.aligned.m16n8k16.row.col.f32.f16.f16.f32 "
        "{%0,%1,%2,%3}, {%4,%5,%6,%7}, {%8,%9}, {%0,%1,%2,%3};\n"
        : "+f"(c[0]), "+f"(c[1]), "+f"(c[2]), "+f"(c[3])
        : "r"(a[0]), "r"(a[1]), "r"(a[2]), "r"(a[3]), "r"(b[0]), "r"(b[1]));
}

// ---------------------------------------------------------------- prep
__global__ void prep_kernel(const float* __restrict__ Whh,
                            const float* __restrict__ bih,
                            const float* __restrict__ bhh) {
    int g = blockIdx.x * blockDim.x + threadIdx.x;
    if (g < GATES) {
        g_bias[g] = bih[g] + bhh[g];
        for (int k = 0; k < HID; k++)
            g_WhhT[k * GATES + g] = Whh[g * HID + k];
    }
}

// W_ih row-major f32 -> fp16 hi/lo, K padded to 2176 (pad = 0)
__global__ void wprep_kernel(const float* __restrict__ Wih) {
    int row = blockIdx.x;   // 0..511
    for (int col = threadIdx.x; col < KPAD; col += blockDim.x) {
        float v = (col < LSDIM) ? Wih[(size_t)row * LSDIM + col] : 0.0f;
        __half hi = __float2half_rn(v);
        __half lo = __float2half_rn(v - __half2float(hi));
        g_Bhi[(size_t)row * KPAD + col] = hi;
        g_Blo[(size_t)row * KPAD + col] = lo;
    }
}

// ---------------------------------------------------------------- K1: logsig
#define PSTRIDE 101

__global__ __launch_bounds__(256) void logsig_kernel(const float* __restrict__ x) {
    const int bs = blockIdx.x;           // 0..799
    const int b = bs / NSEG, s = bs % NSEG;
    const int tid = threadIdx.x;

    __shared__ float p[C][PSTRIDE];      // p[c][t*25+v]
    __shared__ uint8_t s_iu[LEVY], s_ju[LEVY];

    for (int idx = tid; idx < C * (SEGLEN * VV); idx += 256) {
        int c = idx / (SEGLEN * VV);
        int r = idx % (SEGLEN * VV);     // r = t*VV + v
        p[c][r] = x[(((size_t)b * C + c) * TT + s * SEGLEN) * VV + r];
    }
    for (int k = tid; k < LEVY; k += 256) {
        int i = 0, rem = k;
        while (rem >= (C - 1 - i)) { rem -= (C - 1 - i); i++; }
        s_iu[k] = (uint8_t)i;
        s_ju[k] = (uint8_t)(i + 1 + rem);
    }
    __syncthreads();

    for (int v = 0; v < VV; v++) {
        const size_t row = ((size_t)(b * VV + v) * NSEG + s);
        __half* oh = g_A + row * KPAD;

        for (int k = tid; k < LSDIM; k += 256) {
            float val;
            if (k < C) {
                val = p[k][3 * VV + v] - p[k][v];
            } else if (k < C + LEVY) {
                int i = s_iu[k - C], j = s_ju[k - C];
                float si = p[i][v], sj = p[j][v];
                float a = 0.0f;
#pragma unroll
                for (int t = 0; t < SEGLEN - 1; t++) {
                    float pit = p[i][t * VV + v], pjt = p[j][t * VV + v];
                    float devi = pit - si;
                    float devj = pjt - sj;
                    float inci = p[i][(t + 1) * VV + v] - pit;
                    float incj = p[j][(t + 1) * VV + v] - pjt;
                    a += devi * incj - devj * inci;
                }
                val = 0.5f * a;
            } else {
                val = p[k - C - LEVY][v];
            }
            oh[k] = __float2half_rn(val);
        }
    }
}

// ---------------------------------------------------------------- K2: fp16 mma GEMM
// CTA tile M=128 x N=128, BK=32 fp16, 8 warps (warp tile 64x32), 2-stage cp.async.
// acc += A*Bhi + A*Blo  (same f32 accumulator; exact sum of the two products)
// Only error source: fp16 rounding of A (~2^-12 per element).
#define BKE       32                 // K elems per stage
#define SROW      40                 // smem row stride in fp16 elems (80 B)
#define ARR_BYTES (128 * SROW * 2)   // 10240 B per array
#define OFF_A     0
#define OFF_BHI   (ARR_BYTES)
#define OFF_BLO   (2 * ARR_BYTES)
#define STG       (3 * ARR_BYTES)    // 30720 B per stage
#define NSTAGE    2
#define GEMM_SMEM (NSTAGE * STG)     // 61440 B

extern __shared__ char dynsm[];

static __device__ __forceinline__ void load_stage(int tid, int bm, int bn, int s,
                                                  uint32_t sbase) {
    const size_t kb = (size_t)s * (BKE * 2);   // byte offset into a fp16 row
#pragma unroll
    for (int i = 0; i < 2; i++) {
        int ch  = tid + i * 256;     // 0..511 : 128 rows x 4 chunks(16B)
        int row = ch >> 2;
        int c   = ch & 3;
        uint32_t dst = (uint32_t)(row * (SROW * 2) + c * 16);
        size_t gA = (size_t)(bm + row) * ROWB + kb + c * 16;
        size_t gB = (size_t)(bn + row) * ROWB + kb + c * 16;
        cp16(sbase + OFF_A   + dst, (const char*)g_A   + gA);
        cp16(sbase + OFF_BHI + dst, (const char*)g_Bhi + gB);
        cp16(sbase + OFF_BLO + dst, (const char*)g_Blo + gB);
    }
    CP_COMMIT();
}

__global__ __launch_bounds__(256, 2) void gemm_mma_kernel() {
    __shared__ float s_bias[128];

    const int tid  = threadIdx.x;
    const int bn   = blockIdx.x * 128;   // N fastest: wave shares A tiles in L2
    const int bm   = blockIdx.y * 128;
    const int lane = tid & 31;
    const int wid  = tid >> 5;
    const int wm   = (wid >> 2) * 64;    // warp M origin (0 or 64)
    const int wn   = (wid & 3) * 32;     // warp N origin

    const uint32_t sbase = smem_u32(dynsm);

    if (tid < 128) s_bias[tid] = g_bias[bn + tid];

    // ldmatrix per-lane address components
    const int rowA = wm + (lane & 7) + (((lane >> 3) & 1) << 3);
    const int colA = ((lane >> 4) & 1) << 3;
    const int rowB = wn + (lane & 7) + (((lane >> 4) & 1) << 3);
    const int colB = ((lane >> 3) & 1) << 3;

    float acc[4][4][4];
#pragma unroll
    for (int f = 0; f < 4; f++)
#pragma unroll
        for (int n = 0; n < 4; n++)
#pragma unroll
            for (int q = 0; q < 4; q++) acc[f][n][q] = 0.0f;

    // prologue: stage 0
    load_stage(tid, bm, bn, 0, sbase);

    for (int s = 0; s < KSTAGES; s++) {
        CP_WAIT0();          // stage s is the only pending group -> resident
        __syncthreads();     // visibility + all warps done computing stage s-1

        if (s + 1 < KSTAGES) // prefetch next stage into the other buffer
            load_stage(tid, bm, bn, s + 1, sbase + (uint32_t)((s + 1) & 1) * STG);

        const uint32_t buf = sbase + (uint32_t)(s & 1) * STG;
#pragma unroll
        for (int kk = 0; kk < BKE; kk += 16) {
            uint32_t bh[2][4], bl[2][4];
#pragma unroll
            for (int p = 0; p < 2; p++) {
                uint32_t off = (uint32_t)(((rowB + 16 * p) * SROW + colB + kk) * 2);
                ldsm4(bh[p], buf + OFF_BHI + off);
                ldsm4(bl[p], buf + OFF_BLO + off);
            }
#pragma unroll
            for (int f = 0; f < 4; f++) {
                uint32_t ah[4];
                uint32_t off = (uint32_t)(((rowA + 16 * f) * SROW + colA + kk) * 2);
                ldsm4(ah, buf + OFF_A + off);
#pragma unroll
                for (int n = 0; n < 4; n++) {
                    const uint32_t* Bh = &bh[n >> 1][(n & 1) * 2];
                    const uint32_t* Bl = &bl[n >> 1][(n & 1) * 2];
                    mma16816(acc[f][n], ah, Bh);
                    mma16816(acc[f][n], ah, Bl);
                }
            }
        }
    }

    // epilogue: acc rows r0 = base + lane/4, r1 = r0 + 8; cols 2*(lane%4)+{0,1}
    const int r0base = bm + wm + (lane >> 2);
    const int cloc   = wn + 2 * (lane & 3);
#pragma unroll
    for (int f = 0; f < 4; f++) {
        int r0 = r0base + f * 16;
        int r1 = r0 + 8;
#pragma unroll
        for (int n = 0; n < 4; n++) {
            int cl = cloc + n * 8;
            if (r0 < MROWS) {
                float2 v;
                v.x = acc[f][n][0] + s_bias[cl];
                v.y = acc[f][n][1] + s_bias[cl + 1];
                *(float2*)&g_xproj[(size_t)r0 * GATES + bn + cl] = v;
            }
            if (r1 < MROWS) {
                float2 v;
                v.x = acc[f][n][2] + s_bias[cl];
                v.y = acc[f][n][3] + s_bias[cl + 1];
                *(float2*)&g_xproj[(size_t)r1 * GATES + bn + cl] = v;
            }
        }
    }
}

// ---------------------------------------------------------------- K3: LSTM
#define REGK 96
#define TAILK 32
#define LSTM_SMEM (TAILK * GATES * 4)

__global__ __launch_bounds__(512, 1) void lstm_kernel(float* __restrict__ out) {
    const int g = threadIdx.x;
    const int n0 = blockIdx.x * 4;

    __shared__ float4 hs[HID];
    __shared__ float  cs[4][HID];
    __shared__ float  gsm[4][GATES];
    float* sWtail = (float*)dynsm;   // [TAILK][GATES]

    float w[REGK];
#pragma unroll
    for (int k = 0; k < REGK; k++) w[k] = g_WhhT[k * GATES + g];
#pragma unroll
    for (int kk = 0; kk < TAILK; kk++)
        sWtail[kk * GATES + g] = g_WhhT[(REGK + kk) * GATES + g];

    if (g < HID) {
        hs[g] = make_float4(0.f, 0.f, 0.f, 0.f);
        cs[0][g] = 0.f; cs[1][g] = 0.f; cs[2][g] = 0.f; cs[3][g] = 0.f;
    }
    __syncthreads();

    const float* xp = g_xproj + (size_t)n0 * NSEG * GATES + g;

    const int m_  = g >> 7;
    const int hid = g & 127;
    const int n   = n0 + m_;
    const int b   = n / VV;
    const int v   = n % VV;
    float* outp = out + ((size_t)(b * HID + hid) * NSEG) * VV + v;

    for (int s = 0; s < NSEG; s++) {
        float a0 = xp[(0 * NSEG + s) * GATES];
        float a1 = xp[(1 * NSEG + s) * GATES];
        float a2 = xp[(2 * NSEG + s) * GATES];
        float a3 = xp[(3 * NSEG + s) * GATES];
#pragma unroll
        for (int k = 0; k < REGK; k++) {
            float4 h4 = hs[k];
            float wk = w[k];
            a0 += h4.x * wk; a1 += h4.y * wk; a2 += h4.z * wk; a3 += h4.w * wk;
        }
#pragma unroll
        for (int kk = 0; kk < TAILK; kk++) {
            float4 h4 = hs[REGK + kk];
            float wk = sWtail[kk * GATES + g];
            a0 += h4.x * wk; a1 += h4.y * wk; a2 += h4.z * wk; a3 += h4.w * wk;
        }
        gsm[0][g] = a0; gsm[1][g] = a1; gsm[2][g] = a2; gsm[3][g] = a3;
        __syncthreads();

        {
            float gi = gsm[m_][hid];
            float gf = gsm[m_][HID + hid];
            float gg = gsm[m_][2 * HID + hid];
            float go = gsm[m_][3 * HID + hid];
            float c  = cs[m_][hid];
            float cn = fast_sigmoid(gf) * c + fast_sigmoid(gi) * fast_tanh(gg);
            float h  = fast_sigmoid(go) * fast_tanh(cn);
            cs[m_][hid] = cn;
            ((float*)&hs[hid])[m_] = h;
            outp[s * VV] = h;
        }
        __syncthreads();
    }
}

// ---------------------------------------------------------------- launch
extern "C" void kernel_launch(void* const* d_in, const int* in_sizes, int n_in,
                              void* d_out, int out_size) {
    const float* x   = (const float*)d_in[0];
    const float* Wih = (const float*)d_in[1];
    const float* Whh = (const float*)d_in[2];
    const float* bih = (const float*)d_in[3];
    const float* bhh = (const float*)d_in[4];
    float* out = (float*)d_out;

    cudaFuncSetAttribute(gemm_mma_kernel,
                         cudaFuncAttributeMaxDynamicSharedMemorySize, GEMM_SMEM);
    cudaFuncSetAttribute(lstm_kernel,
                         cudaFuncAttributeMaxDynamicSharedMemorySize, LSTM_SMEM);

    prep_kernel<<<2, 256>>>(Whh, bih, bhh);
    wprep_kernel<<<GATES, 256>>>(Wih);
    logsig_kernel<<<16 * NSEG, 256>>>(x);
    dim3 grid(GATES / 128, MPAD / 128);   // (4, 157), N fastest
    gemm_mma_kernel<<<grid, 256, GEMM_SMEM>>>();
    lstm_kernel<<<NSEQ / 4, 512, LSTM_SMEM>>>(out);
}

// round 15
// speedup vs baseline: 2.8522x; 1.2251x over previous
#include <cuda_runtime.h>
#include <cuda_fp16.h>
#include <math.h>
#include <stdint.h>

// ---------------------------------------------------------------- constants
#define NSEQ      400
#define NSEG      50
#define SEGLEN    4
#define C         64
#define TT        200
#define VV        25
#define HID       128
#define GATES     512
#define LEVY      2016
#define LSDIM     2144
#define MROWS     20000
#define MPAD      20096        // 157*128
#define KPAD      2176         // 68*32
#define KSTAGES   68           // K stages of 32 fp16 elems
#define ROWB      (KPAD*2)     // bytes per fp16 row

// ---------------------------------------------------------------- scratch
__device__ __half g_A[(size_t)MPAD * KPAD];      // logsig features (fp16)
__device__ __half g_B[(size_t)GATES * KPAD];     // W_ih (fp16)
__device__ float  g_xproj[(size_t)MROWS * GATES];
__device__ float  g_WhhT[HID * GATES];
__device__ float  g_bias[GATES];

__device__ __forceinline__ float ex2f(float x) {
    float y; asm("ex2.approx.f32 %0, %1;" : "=f"(y) : "f"(x)); return y;
}
__device__ __forceinline__ float rcpf(float x) {
    float y; asm("rcp.approx.f32 %0, %1;" : "=f"(y) : "f"(x)); return y;
}
__device__ __forceinline__ float fast_sigmoid(float x) {
    return rcpf(1.0f + ex2f(-1.4426950408889634f * x));
}
__device__ __forceinline__ float fast_tanh(float x) {
    return 2.0f * rcpf(1.0f + ex2f(-2.8853900817779268f * x)) - 1.0f;
}

__device__ __forceinline__ uint32_t smem_u32(const void* p) {
    uint32_t a;
    asm("{ .reg .u64 t; cvta.to.shared.u64 t, %1; cvt.u32.u64 %0, t; }" : "=r"(a) : "l"(p));
    return a;
}

static __device__ __forceinline__ void cp16(uint32_t s, const void* g) {
    asm volatile("cp.async.cg.shared.global [%0], [%1], 16;\n" :: "r"(s), "l"(g));
}
#define CP_COMMIT()  asm volatile("cp.async.commit_group;\n" ::: "memory")
#define CP_WAIT0()   asm volatile("cp.async.wait_group 0;\n" ::: "memory")

static __device__ __forceinline__ void ldsm4(uint32_t* r, uint32_t addr) {
    asm volatile("ldmatrix.sync.aligned.m8n8.x4.shared.b16 {%0,%1,%2,%3}, [%4];\n"
                 : "=r"(r[0]), "=r"(r[1]), "=r"(r[2]), "=r"(r[3]) : "r"(addr));
}

static __device__ __forceinline__ void mma16816(float* c, const uint32_t* a,
                                                const uint32_t* b) {
    asm volatile(
        "mma.sync.aligned.m16n8k16.row.col.f32.f16.f16.f32 "
        "{%0,%1,%2,%3}, {%4,%5,%6,%7}, {%8,%9}, {%0,%1,%2,%3};\n"
        : "+f"(c[0]), "+f"(c[1]), "+f"(c[2]), "+f"(c[3])
        : "r"(a[0]), "r"(a[1]), "r"(a[2]), "r"(a[3]), "r"(b[0]), "r"(b[1]));
}

// ---------------------------------------------------------------- prep
__global__ void prep_kernel(const float* __restrict__ Whh,
                            const float* __restrict__ bih,
                            const float* __restrict__ bhh) {
    int g = blockIdx.x * blockDim.x + threadIdx.x;
    if (g < GATES) {
        g_bias[g] = bih[g] + bhh[g];
        for (int k = 0; k < HID; k++)
            g_WhhT[k * GATES + g] = Whh[g * HID + k];
    }
}

// W_ih row-major f32 -> fp16, K padded to 2176 (pad = 0)
__global__ void wprep_kernel(const float* __restrict__ Wih) {
    int row = blockIdx.x;   // 0..511
    for (int col = threadIdx.x; col < KPAD; col += blockDim.x) {
        float v = (col < LSDIM) ? Wih[(size_t)row * LSDIM + col] : 0.0f;
        g_B[(size_t)row * KPAD + col] = __float2half_rn(v);
    }
}

// ---------------------------------------------------------------- K1: logsig
#define PSTRIDE 101

__global__ __launch_bounds__(256) void logsig_kernel(const float* __restrict__ x) {
    const int bs = blockIdx.x;           // 0..799
    const int b = bs / NSEG, s = bs % NSEG;
    const int tid = threadIdx.x;

    __shared__ float p[C][PSTRIDE];      // p[c][t*25+v]
    __shared__ uint8_t s_iu[LEVY], s_ju[LEVY];

    for (int idx = tid; idx < C * (SEGLEN * VV); idx += 256) {
        int c = idx / (SEGLEN * VV);
        int r = idx % (SEGLEN * VV);     // r = t*VV + v
        p[c][r] = x[(((size_t)b * C + c) * TT + s * SEGLEN) * VV + r];
    }
    for (int k = tid; k < LEVY; k += 256) {
        int i = 0, rem = k;
        while (rem >= (C - 1 - i)) { rem -= (C - 1 - i); i++; }
        s_iu[k] = (uint8_t)i;
        s_ju[k] = (uint8_t)(i + 1 + rem);
    }
    __syncthreads();

    for (int v = 0; v < VV; v++) {
        const size_t row = ((size_t)(b * VV + v) * NSEG + s);
        __half* oh = g_A + row * KPAD;

        for (int k = tid; k < LSDIM; k += 256) {
            float val;
            if (k < C) {
                val = p[k][3 * VV + v] - p[k][v];
            } else if (k < C + LEVY) {
                int i = s_iu[k - C], j = s_ju[k - C];
                float si = p[i][v], sj = p[j][v];
                float a = 0.0f;
#pragma unroll
                for (int t = 0; t < SEGLEN - 1; t++) {
                    float pit = p[i][t * VV + v], pjt = p[j][t * VV + v];
                    float devi = pit - si;
                    float devj = pjt - sj;
                    float inci = p[i][(t + 1) * VV + v] - pit;
                    float incj = p[j][(t + 1) * VV + v] - pjt;
                    a += devi * incj - devj * inci;
                }
                val = 0.5f * a;
            } else {
                val = p[k - C - LEVY][v];
            }
            oh[k] = __float2half_rn(val);
        }
    }
}

// ---------------------------------------------------------------- K2: fp16 mma GEMM
// CTA tile M=128 x N=128, BK=32 fp16, 8 warps (warp tile 64x32), 2-stage cp.async.
// Plain fp16 x fp16 -> f32:  ONE mma per fragment pair.
#define BKE       32                 // K elems per stage
#define SROW      40                 // smem row stride in fp16 elems (80 B)
#define ARR_BYTES (128 * SROW * 2)   // 10240 B per array
#define OFF_A     0
#define OFF_B     (ARR_BYTES)
#define STG       (2 * ARR_BYTES)    // 20480 B per stage
#define NSTAGE    2
#define GEMM_SMEM (NSTAGE * STG)     // 40960 B

extern __shared__ char dynsm[];

static __device__ __forceinline__ void load_stage(int tid, int bm, int bn, int s,
                                                  uint32_t sbase) {
    const size_t kb = (size_t)s * (BKE * 2);   // byte offset into a fp16 row
#pragma unroll
    for (int i = 0; i < 2; i++) {
        int ch  = tid + i * 256;     // 0..511 : 128 rows x 4 chunks(16B)
        int row = ch >> 2;
        int c   = ch & 3;
        uint32_t dst = (uint32_t)(row * (SROW * 2) + c * 16);
        size_t gA = (size_t)(bm + row) * ROWB + kb + c * 16;
        size_t gB = (size_t)(bn + row) * ROWB + kb + c * 16;
        cp16(sbase + OFF_A + dst, (const char*)g_A + gA);
        cp16(sbase + OFF_B + dst, (const char*)g_B + gB);
    }
    CP_COMMIT();
}

__global__ __launch_bounds__(256, 2) void gemm_mma_kernel() {
    __shared__ float s_bias[128];

    const int tid  = threadIdx.x;
    const int bn   = blockIdx.x * 128;   // N fastest: wave shares A tiles in L2
    const int bm   = blockIdx.y * 128;
    const int lane = tid & 31;
    const int wid  = tid >> 5;
    const int wm   = (wid >> 2) * 64;    // warp M origin (0 or 64)
    const int wn   = (wid & 3) * 32;     // warp N origin

    const uint32_t sbase = smem_u32(dynsm);

    if (tid < 128) s_bias[tid] = g_bias[bn + tid];

    // ldmatrix per-lane address components
    const int rowA = wm + (lane & 7) + (((lane >> 3) & 1) << 3);
    const int colA = ((lane >> 4) & 1) << 3;
    const int rowB = wn + (lane & 7) + (((lane >> 4) & 1) << 3);
    const int colB = ((lane >> 3) & 1) << 3;

    float acc[4][4][4];
#pragma unroll
    for (int f = 0; f < 4; f++)
#pragma unroll
        for (int n = 0; n < 4; n++)
#pragma unroll
            for (int q = 0; q < 4; q++) acc[f][n][q] = 0.0f;

    // prologue: stage 0
    load_stage(tid, bm, bn, 0, sbase);

    for (int s = 0; s < KSTAGES; s++) {
        CP_WAIT0();          // stage s is the only pending group -> resident
        __syncthreads();     // visibility + all warps done computing stage s-1

        if (s + 1 < KSTAGES) // prefetch next stage into the other buffer
            load_stage(tid, bm, bn, s + 1, sbase + (uint32_t)((s + 1) & 1) * STG);

        const uint32_t buf = sbase + (uint32_t)(s & 1) * STG;
#pragma unroll
        for (int kk = 0; kk < BKE; kk += 16) {
            uint32_t bfr[2][4];
#pragma unroll
            for (int p = 0; p < 2; p++) {
                uint32_t off = (uint32_t)(((rowB + 16 * p) * SROW + colB + kk) * 2);
                ldsm4(bfr[p], buf + OFF_B + off);
            }
#pragma unroll
            for (int f = 0; f < 4; f++) {
                uint32_t ah[4];
                uint32_t off = (uint32_t)(((rowA + 16 * f) * SROW + colA + kk) * 2);
                ldsm4(ah, buf + OFF_A + off);
#pragma unroll
                for (int n = 0; n < 4; n++)
                    mma16816(acc[f][n], ah, &bfr[n >> 1][(n & 1) * 2]);
            }
        }
    }

    // epilogue: acc rows r0 = base + lane/4, r1 = r0 + 8; cols 2*(lane%4)+{0,1}
    const int r0base = bm + wm + (lane >> 2);
    const int cloc   = wn + 2 * (lane & 3);
#pragma unroll
    for (int f = 0; f < 4; f++) {
        int r0 = r0base + f * 16;
        int r1 = r0 + 8;
#pragma unroll
        for (int n = 0; n < 4; n++) {
            int cl = cloc + n * 8;
            if (r0 < MROWS) {
                float2 v;
                v.x = acc[f][n][0] + s_bias[cl];
                v.y = acc[f][n][1] + s_bias[cl + 1];
                *(float2*)&g_xproj[(size_t)r0 * GATES + bn + cl] = v;
            }
            if (r1 < MROWS) {
                float2 v;
                v.x = acc[f][n][2] + s_bias[cl];
                v.y = acc[f][n][3] + s_bias[cl + 1];
                *(float2*)&g_xproj[(size_t)r1 * GATES + bn + cl] = v;
            }
        }
    }
}

// ---------------------------------------------------------------- K3: LSTM
#define REGK 96
#define TAILK 32
#define LSTM_SMEM (TAILK * GATES * 4)

__global__ __launch_bounds__(512, 1) void lstm_kernel(float* __restrict__ out) {
    const int g = threadIdx.x;
    const int n0 = blockIdx.x * 4;

    __shared__ float4 hs[HID];
    __shared__ float  cs[4][HID];
    __shared__ float  gsm[4][GATES];
    float* sWtail = (float*)dynsm;   // [TAILK][GATES]

    float w[REGK];
#pragma unroll
    for (int k = 0; k < REGK; k++) w[k] = g_WhhT[k * GATES + g];
#pragma unroll
    for (int kk = 0; kk < TAILK; kk++)
        sWtail[kk * GATES + g] = g_WhhT[(REGK + kk) * GATES + g];

    if (g < HID) {
        hs[g] = make_float4(0.f, 0.f, 0.f, 0.f);
        cs[0][g] = 0.f; cs[1][g] = 0.f; cs[2][g] = 0.f; cs[3][g] = 0.f;
    }
    __syncthreads();

    const float* xp = g_xproj + (size_t)n0 * NSEG * GATES + g;

    const int m_  = g >> 7;
    const int hid = g & 127;
    const int n   = n0 + m_;
    const int b   = n / VV;
    const int v   = n % VV;
    float* outp = out + ((size_t)(b * HID + hid) * NSEG) * VV + v;

    for (int s = 0; s < NSEG; s++) {
        float a0 = xp[(0 * NSEG + s) * GATES];
        float a1 = xp[(1 * NSEG + s) * GATES];
        float a2 = xp[(2 * NSEG + s) * GATES];
        float a3 = xp[(3 * NSEG + s) * GATES];
#pragma unroll
        for (int k = 0; k < REGK; k++) {
            float4 h4 = hs[k];
            float wk = w[k];
            a0 += h4.x * wk; a1 += h4.y * wk; a2 += h4.z * wk; a3 += h4.w * wk;
        }
#pragma unroll
        for (int kk = 0; kk < TAILK; kk++) {
            float4 h4 = hs[REGK + kk];
            float wk = sWtail[kk * GATES + g];
            a0 += h4.x * wk; a1 += h4.y * wk; a2 += h4.z * wk; a3 += h4.w * wk;
        }
        gsm[0][g] = a0; gsm[1][g] = a1; gsm[2][g] = a2; gsm[3][g] = a3;
        __syncthreads();

        {
            float gi = gsm[m_][hid];
            float gf = gsm[m_][HID + hid];
            float gg = gsm[m_][2 * HID + hid];
            float go = gsm[m_][3 * HID + hid];
            float c  = cs[m_][hid];
            float cn = fast_sigmoid(gf) * c + fast_sigmoid(gi) * fast_tanh(gg);
            float h  = fast_sigmoid(go) * fast_tanh(cn);
            cs[m_][hid] = cn;
            ((float*)&hs[hid])[m_] = h;
            outp[s * VV] = h;
        }
        __syncthreads();
    }
}

// ---------------------------------------------------------------- launch
extern "C" void kernel_launch(void* const* d_in, const int* in_sizes, int n_in,
                              void* d_out, int out_size) {
    const float* x   = (const float*)d_in[0];
    const float* Wih = (const float*)d_in[1];
    const float* Whh = (const float*)d_in[2];
    const float* bih = (const float*)d_in[3];
    const float* bhh = (const float*)d_in[4];
    float* out = (float*)d_out;

    cudaFuncSetAttribute(gemm_mma_kernel,
                         cudaFuncAttributeMaxDynamicSharedMemorySize, GEMM_SMEM);
    cudaFuncSetAttribute(lstm_kernel,
                         cudaFuncAttributeMaxDynamicSharedMemorySize, LSTM_SMEM);

    prep_kernel<<<2, 256>>>(Whh, bih, bhh);
    wprep_kernel<<<GATES, 256>>>(Wih);
    logsig_kernel<<<16 * NSEG, 256>>>(x);
    dim3 grid(GATES / 128, MPAD / 128);   // (4, 157), N fastest
    gemm_mma_kernel<<<grid, 256, GEMM_SMEM>>>();
    lstm_kernel<<<NSEQ / 4, 512, LSTM_SMEM>>>(out);
}

// round 16
// speedup vs baseline: 3.1896x; 1.1183x over previous
#include <cuda_runtime.h>
#include <cuda_fp16.h>
#include <math.h>
#include <stdint.h>

// ---------------------------------------------------------------- constants
#define NSEQ      400
#define NSEG      50
#define SEGLEN    4
#define C         64
#define TT        200
#define VV        25
#define HID       128
#define GATES     512
#define LEVY      2016
#define LSDIM     2144
#define MROWS     20000
#define MPAD      20096        // 157*128
#define KPAD      2176         // 68*32
#define KSTAGES   68           // K stages of 32 fp16 elems
#define ROWB      (KPAD*2)     // bytes per fp16 row

// ---------------------------------------------------------------- scratch
__device__ __half g_A[(size_t)MPAD * KPAD];      // logsig features (fp16)
__device__ __half g_B[(size_t)GATES * KPAD];     // W_ih (fp16)
__device__ float  g_xproj[(size_t)MROWS * GATES];
__device__ float  g_WhhT[HID * GATES];
__device__ float  g_bias[GATES];

__device__ __forceinline__ float ex2f(float x) {
    float y; asm("ex2.approx.f32 %0, %1;" : "=f"(y) : "f"(x)); return y;
}
__device__ __forceinline__ float rcpf(float x) {
    float y; asm("rcp.approx.f32 %0, %1;" : "=f"(y) : "f"(x)); return y;
}
__device__ __forceinline__ float fast_sigmoid(float x) {
    return rcpf(1.0f + ex2f(-1.4426950408889634f * x));
}
__device__ __forceinline__ float fast_tanh(float x) {
    return 2.0f * rcpf(1.0f + ex2f(-2.8853900817779268f * x)) - 1.0f;
}

__device__ __forceinline__ uint32_t smem_u32(const void* p) {
    uint32_t a;
    asm("{ .reg .u64 t; cvta.to.shared.u64 t, %1; cvt.u32.u64 %0, t; }" : "=r"(a) : "l"(p));
    return a;
}

static __device__ __forceinline__ void cp16(uint32_t s, const void* g) {
    asm volatile("cp.async.cg.shared.global [%0], [%1], 16;\n" :: "r"(s), "l"(g));
}
#define CP_COMMIT()  asm volatile("cp.async.commit_group;\n" ::: "memory")
#define CP_WAIT0()   asm volatile("cp.async.wait_group 0;\n" ::: "memory")

static __device__ __forceinline__ void ldsm4(uint32_t* r, uint32_t addr) {
    asm volatile("ldmatrix.sync.aligned.m8n8.x4.shared.b16 {%0,%1,%2,%3}, [%4];\n"
                 : "=r"(r[0]), "=r"(r[1]), "=r"(r[2]), "=r"(r[3]) : "r"(addr));
}

static __device__ __forceinline__ void mma16816(float* c, const uint32_t* a,
                                                const uint32_t* b) {
    asm volatile(
        "mma.sync.aligned.m16n8k16.row.col.f32.f16.f16.f32 "
        "{%0,%1,%2,%3}, {%4,%5,%6,%7}, {%8,%9}, {%0,%1,%2,%3};\n"
        : "+f"(c[0]), "+f"(c[1]), "+f"(c[2]), "+f"(c[3])
        : "r"(a[0]), "r"(a[1]), "r"(a[2]), "r"(a[3]), "r"(b[0]), "r"(b[1]));
}

// ---------------------------------------------------------------- prep
// 128 blocks: block k transposes W_hh column k; block 0 also folds biases.
__global__ __launch_bounds__(512) void prep_kernel(const float* __restrict__ Whh,
                                                   const float* __restrict__ bih,
                                                   const float* __restrict__ bhh) {
    const int k = blockIdx.x;      // 0..127
    const int g = threadIdx.x;     // 0..511
    g_WhhT[k * GATES + g] = Whh[g * HID + k];
    if (k == 0) g_bias[g] = bih[g] + bhh[g];
}

// W_ih row-major f32 -> fp16, K padded to 2176 (pad = 0)
__global__ void wprep_kernel(const float* __restrict__ Wih) {
    int row = blockIdx.x;   // 0..511
    for (int col = threadIdx.x; col < KPAD; col += blockDim.x) {
        float v = (col < LSDIM) ? Wih[(size_t)row * LSDIM + col] : 0.0f;
        g_B[(size_t)row * KPAD + col] = __float2half_rn(v);
    }
}

// ---------------------------------------------------------------- K1: logsig
#define PSTRIDE 101

__global__ __launch_bounds__(256) void logsig_kernel(const float* __restrict__ x) {
    const int bs = blockIdx.x;           // 0..799
    const int b = bs / NSEG, s = bs % NSEG;
    const int tid = threadIdx.x;

    __shared__ float p[C][PSTRIDE];      // p[c][t*25+v]
    __shared__ uint8_t s_iu[LEVY], s_ju[LEVY];

    for (int idx = tid; idx < C * (SEGLEN * VV); idx += 256) {
        int c = idx / (SEGLEN * VV);
        int r = idx % (SEGLEN * VV);     // r = t*VV + v
        p[c][r] = x[(((size_t)b * C + c) * TT + s * SEGLEN) * VV + r];
    }
    for (int k = tid; k < LEVY; k += 256) {
        int i = 0, rem = k;
        while (rem >= (C - 1 - i)) { rem -= (C - 1 - i); i++; }
        s_iu[k] = (uint8_t)i;
        s_ju[k] = (uint8_t)(i + 1 + rem);
    }
    __syncthreads();

    for (int v = 0; v < VV; v++) {
        const size_t row = ((size_t)(b * VV + v) * NSEG + s);
        __half* oh = g_A + row * KPAD;

        for (int k = tid; k < LSDIM; k += 256) {
            float val;
            if (k < C) {
                val = p[k][3 * VV + v] - p[k][v];
            } else if (k < C + LEVY) {
                int i = s_iu[k - C], j = s_ju[k - C];
                float si = p[i][v], sj = p[j][v];
                float a = 0.0f;
#pragma unroll
                for (int t = 0; t < SEGLEN - 1; t++) {
                    float pit = p[i][t * VV + v], pjt = p[j][t * VV + v];
                    float devi = pit - si;
                    float devj = pjt - sj;
                    float inci = p[i][(t + 1) * VV + v] - pit;
                    float incj = p[j][(t + 1) * VV + v] - pjt;
                    a += devi * incj - devj * inci;
                }
                val = 0.5f * a;
            } else {
                val = p[k - C - LEVY][v];
            }
            oh[k] = __float2half_rn(val);
        }
    }
}

// ---------------------------------------------------------------- K2: fp16 mma GEMM
// CTA tile M=128 x N=128, BK=32 fp16, 8 warps (warp tile 64x32), 2-stage cp.async.
// Plain fp16 x fp16 -> f32:  ONE mma per fragment pair.
#define BKE       32                 // K elems per stage
#define SROW      40                 // smem row stride in fp16 elems (80 B)
#define ARR_BYTES (128 * SROW * 2)   // 10240 B per array
#define OFF_A     0
#define OFF_B     (ARR_BYTES)
#define STG       (2 * ARR_BYTES)    // 20480 B per stage
#define NSTAGE    2
#define GEMM_SMEM (NSTAGE * STG)     // 40960 B

extern __shared__ char dynsm[];

static __device__ __forceinline__ void load_stage(int tid, int bm, int bn, int s,
                                                  uint32_t sbase) {
    const size_t kb = (size_t)s * (BKE * 2);   // byte offset into a fp16 row
#pragma unroll
    for (int i = 0; i < 2; i++) {
        int ch  = tid + i * 256;     // 0..511 : 128 rows x 4 chunks(16B)
        int row = ch >> 2;
        int c   = ch & 3;
        uint32_t dst = (uint32_t)(row * (SROW * 2) + c * 16);
        size_t gA = (size_t)(bm + row) * ROWB + kb + c * 16;
        size_t gB = (size_t)(bn + row) * ROWB + kb + c * 16;
        cp16(sbase + OFF_A + dst, (const char*)g_A + gA);
        cp16(sbase + OFF_B + dst, (const char*)g_B + gB);
    }
    CP_COMMIT();
}

__global__ __launch_bounds__(256, 2) void gemm_mma_kernel() {
    __shared__ float s_bias[128];

    const int tid  = threadIdx.x;
    const int bn   = blockIdx.x * 128;   // N fastest: wave shares A tiles in L2
    const int bm   = blockIdx.y * 128;
    const int lane = tid & 31;
    const int wid  = tid >> 5;
    const int wm   = (wid >> 2) * 64;    // warp M origin (0 or 64)
    const int wn   = (wid & 3) * 32;     // warp N origin

    const uint32_t sbase = smem_u32(dynsm);

    if (tid < 128) s_bias[tid] = g_bias[bn + tid];

    // ldmatrix per-lane address components
    const int rowA = wm + (lane & 7) + (((lane >> 3) & 1) << 3);
    const int colA = ((lane >> 4) & 1) << 3;
    const int rowB = wn + (lane & 7) + (((lane >> 4) & 1) << 3);
    const int colB = ((lane >> 3) & 1) << 3;

    float acc[4][4][4];
#pragma unroll
    for (int f = 0; f < 4; f++)
#pragma unroll
        for (int n = 0; n < 4; n++)
#pragma unroll
            for (int q = 0; q < 4; q++) acc[f][n][q] = 0.0f;

    // prologue: stage 0
    load_stage(tid, bm, bn, 0, sbase);

    for (int s = 0; s < KSTAGES; s++) {
        CP_WAIT0();          // stage s is the only pending group -> resident
        __syncthreads();     // visibility + all warps done computing stage s-1

        if (s + 1 < KSTAGES) // prefetch next stage into the other buffer
            load_stage(tid, bm, bn, s + 1, sbase + (uint32_t)((s + 1) & 1) * STG);

        const uint32_t buf = sbase + (uint32_t)(s & 1) * STG;
#pragma unroll
        for (int kk = 0; kk < BKE; kk += 16) {
            uint32_t bfr[2][4];
#pragma unroll
            for (int p = 0; p < 2; p++) {
                uint32_t off = (uint32_t)(((rowB + 16 * p) * SROW + colB + kk) * 2);
                ldsm4(bfr[p], buf + OFF_B + off);
            }
#pragma unroll
            for (int f = 0; f < 4; f++) {
                uint32_t ah[4];
                uint32_t off = (uint32_t)(((rowA + 16 * f) * SROW + colA + kk) * 2);
                ldsm4(ah, buf + OFF_A + off);
#pragma unroll
                for (int n = 0; n < 4; n++)
                    mma16816(acc[f][n], ah, &bfr[n >> 1][(n & 1) * 2]);
            }
        }
    }

    // epilogue: acc rows r0 = base + lane/4, r1 = r0 + 8; cols 2*(lane%4)+{0,1}
    const int r0base = bm + wm + (lane >> 2);
    const int cloc   = wn + 2 * (lane & 3);
#pragma unroll
    for (int f = 0; f < 4; f++) {
        int r0 = r0base + f * 16;
        int r1 = r0 + 8;
#pragma unroll
        for (int n = 0; n < 4; n++) {
            int cl = cloc + n * 8;
            if (r0 < MROWS) {
                float2 v;
                v.x = acc[f][n][0] + s_bias[cl];
                v.y = acc[f][n][1] + s_bias[cl + 1];
                *(float2*)&g_xproj[(size_t)r0 * GATES + bn + cl] = v;
            }
            if (r1 < MROWS) {
                float2 v;
                v.x = acc[f][n][2] + s_bias[cl];
                v.y = acc[f][n][3] + s_bias[cl + 1];
                *(float2*)&g_xproj[(size_t)r1 * GATES + bn + cl] = v;
            }
        }
    }
}

// ---------------------------------------------------------------- K3: LSTM
// 134 blocks x 3 seqs, 512 threads (1 per gate col, 3 accumulators).
// W column split: k<96 in registers, k in [96,128) from dynamic smem.
// Next step's x_proj prefetched into registers before the k-loop.
#define SEQB  3
#define LBLK  134                 // ceil(400/3)
#define REGK  96
#define TAILK 32
#define LSTM_SMEM (TAILK * GATES * 4)

__global__ __launch_bounds__(512, 1) void lstm_kernel(float* __restrict__ out) {
    const int g = threadIdx.x;
    const int n0 = blockIdx.x * SEQB;

    __shared__ float4 hs[HID];        // x,y,z used for the 3 seqs
    __shared__ float  cs[SEQB][HID];
    __shared__ float  gsm[SEQB][GATES];
    float* sWtail = (float*)dynsm;    // [TAILK][GATES]

    float w[REGK];
#pragma unroll
    for (int k = 0; k < REGK; k++) w[k] = g_WhhT[k * GATES + g];
#pragma unroll
    for (int kk = 0; kk < TAILK; kk++)
        sWtail[kk * GATES + g] = g_WhhT[(REGK + kk) * GATES + g];

    if (g < HID) {
        hs[g] = make_float4(0.f, 0.f, 0.f, 0.f);
        cs[0][g] = 0.f; cs[1][g] = 0.f; cs[2][g] = 0.f;
    }
    __syncthreads();

    // clamped row pointers (invalid seqs read seq NSEQ-1 harmlessly)
    const int nc0 = (n0 + 0 < NSEQ) ? n0 + 0 : NSEQ - 1;
    const int nc1 = (n0 + 1 < NSEQ) ? n0 + 1 : NSEQ - 1;
    const int nc2 = (n0 + 2 < NSEQ) ? n0 + 2 : NSEQ - 1;
    const float* xp0 = g_xproj + (size_t)nc0 * NSEG * GATES + g;
    const float* xp1 = g_xproj + (size_t)nc1 * NSEG * GATES + g;
    const float* xp2 = g_xproj + (size_t)nc2 * NSEG * GATES + g;

    const int m_  = g >> 7;           // 0..3 ; update role only for m_ < 3
    const int hid = g & 127;
    const int n   = n0 + m_;
    const bool upd = (m_ < SEQB) && (n < NSEQ);
    float* outp = nullptr;
    if (upd) {
        const int b = n / VV, v = n % VV;
        outp = out + ((size_t)(b * HID + hid) * NSEG) * VV + v;
    }

    float a0 = xp0[0], a1 = xp1[0], a2 = xp2[0];

    for (int s = 0; s < NSEG; s++) {
        // prefetch next step (hidden behind the k-loop)
        float na0 = 0.f, na1 = 0.f, na2 = 0.f;
        if (s + 1 < NSEG) {
            na0 = xp0[(s + 1) * GATES];
            na1 = xp1[(s + 1) * GATES];
            na2 = xp2[(s + 1) * GATES];
        }
#pragma unroll
        for (int k = 0; k < REGK; k++) {
            float4 h4 = hs[k];
            float wk = w[k];
            a0 += h4.x * wk; a1 += h4.y * wk; a2 += h4.z * wk;
        }
#pragma unroll
        for (int kk = 0; kk < TAILK; kk++) {
            float4 h4 = hs[REGK + kk];
            float wk = sWtail[kk * GATES + g];
            a0 += h4.x * wk; a1 += h4.y * wk; a2 += h4.z * wk;
        }
        gsm[0][g] = a0; gsm[1][g] = a1; gsm[2][g] = a2;
        __syncthreads();

        if (upd) {
            float gi = gsm[m_][hid];
            float gf = gsm[m_][HID + hid];
            float gg = gsm[m_][2 * HID + hid];
            float go = gsm[m_][3 * HID + hid];
            float c  = cs[m_][hid];
            float cn = fast_sigmoid(gf) * c + fast_sigmoid(gi) * fast_tanh(gg);
            float h  = fast_sigmoid(go) * fast_tanh(cn);
            cs[m_][hid] = cn;
            ((float*)&hs[hid])[m_] = h;
            outp[s * VV] = h;
        }
        __syncthreads();

        a0 = na0; a1 = na1; a2 = na2;
    }
}

// ---------------------------------------------------------------- launch
extern "C" void kernel_launch(void* const* d_in, const int* in_sizes, int n_in,
                              void* d_out, int out_size) {
    const float* x   = (const float*)d_in[0];
    const float* Wih = (const float*)d_in[1];
    const float* Whh = (const float*)d_in[2];
    const float* bih = (const float*)d_in[3];
    const float* bhh = (const float*)d_in[4];
    float* out = (float*)d_out;

    cudaFuncSetAttribute(gemm_mma_kernel,
                         cudaFuncAttributeMaxDynamicSharedMemorySize, GEMM_SMEM);
    cudaFuncSetAttribute(lstm_kernel,
                         cudaFuncAttributeMaxDynamicSharedMemorySize, LSTM_SMEM);

    prep_kernel<<<HID, 512>>>(Whh, bih, bhh);
    wprep_kernel<<<GATES, 256>>>(Wih);
    logsig_kernel<<<16 * NSEG, 256>>>(x);
    dim3 grid(GATES / 128, MPAD / 128);   // (4, 157), N fastest
    gemm_mma_kernel<<<grid, 256, GEMM_SMEM>>>();
    lstm_kernel<<<LBLK, 512, LSTM_SMEM>>>(out);
}

// round 17
// speedup vs baseline: 3.2658x; 1.0239x over previous
#include <cuda_runtime.h>
#include <cuda_fp16.h>
#include <math.h>
#include <stdint.h>

// ---------------------------------------------------------------- constants
#define NSEQ      400
#define NSEG      50
#define SEGLEN    4
#define C         64
#define TT        200
#define VV        25
#define HID       128
#define GATES     512
#define LEVY      2016
#define LSDIM     2144
#define MROWS     20000
#define MPAD      20096        // 157*128
#define KPAD      2176         // 68*32
#define KSTAGES   68           // K stages of 32 fp16 elems
#define ROWB      (KPAD*2)     // bytes per fp16 row

// ---------------------------------------------------------------- scratch
__device__ __half g_A[(size_t)MPAD * KPAD];      // logsig features (fp16)
__device__ __half g_B[(size_t)GATES * KPAD];     // W_ih (fp16)
__device__ float  g_xproj[(size_t)MROWS * GATES];
__device__ float  g_WhhT[HID * GATES];
__device__ float  g_bias[GATES];

__device__ __forceinline__ float ex2f(float x) {
    float y; asm("ex2.approx.f32 %0, %1;" : "=f"(y) : "f"(x)); return y;
}
__device__ __forceinline__ float rcpf(float x) {
    float y; asm("rcp.approx.f32 %0, %1;" : "=f"(y) : "f"(x)); return y;
}
__device__ __forceinline__ float fast_sigmoid(float x) {
    return rcpf(1.0f + ex2f(-1.4426950408889634f * x));
}
__device__ __forceinline__ float fast_tanh(float x) {
    return 2.0f * rcpf(1.0f + ex2f(-2.8853900817779268f * x)) - 1.0f;
}

__device__ __forceinline__ uint32_t smem_u32(const void* p) {
    uint32_t a;
    asm("{ .reg .u64 t; cvta.to.shared.u64 t, %1; cvt.u32.u64 %0, t; }" : "=r"(a) : "l"(p));
    return a;
}

static __device__ __forceinline__ void cp16(uint32_t s, const void* g) {
    asm volatile("cp.async.cg.shared.global [%0], [%1], 16;\n" :: "r"(s), "l"(g));
}
#define CP_COMMIT()  asm volatile("cp.async.commit_group;\n" ::: "memory")
#define CP_WAIT0()   asm volatile("cp.async.wait_group 0;\n" ::: "memory")

static __device__ __forceinline__ void ldsm4(uint32_t* r, uint32_t addr) {
    asm volatile("ldmatrix.sync.aligned.m8n8.x4.shared.b16 {%0,%1,%2,%3}, [%4];\n"
                 : "=r"(r[0]), "=r"(r[1]), "=r"(r[2]), "=r"(r[3]) : "r"(addr));
}

static __device__ __forceinline__ void mma16816(float* c, const uint32_t* a,
                                                const uint32_t* b) {
    asm volatile(
        "mma.sync.aligned.m16n8k16.row.col.f32.f16.f16.f32 "
        "{%0,%1,%2,%3}, {%4,%5,%6,%7}, {%8,%9}, {%0,%1,%2,%3};\n"
        : "+f"(c[0]), "+f"(c[1]), "+f"(c[2]), "+f"(c[3])
        : "r"(a[0]), "r"(a[1]), "r"(a[2]), "r"(a[3]), "r"(b[0]), "r"(b[1]));
}

// ---------------------------------------------------------------- prep
// 128 blocks: block k transposes W_hh column k; block 0 also folds biases.
__global__ __launch_bounds__(512) void prep_kernel(const float* __restrict__ Whh,
                                                   const float* __restrict__ bih,
                                                   const float* __restrict__ bhh) {
    const int k = blockIdx.x;      // 0..127
    const int g = threadIdx.x;     // 0..511
    g_WhhT[k * GATES + g] = Whh[g * HID + k];
    if (k == 0) g_bias[g] = bih[g] + bhh[g];
}

// W_ih row-major f32 -> fp16, K padded to 2176 (pad = 0)
__global__ void wprep_kernel(const float* __restrict__ Wih) {
    int row = blockIdx.x;   // 0..511
    for (int col = threadIdx.x; col < KPAD; col += blockDim.x) {
        float v = (col < LSDIM) ? Wih[(size_t)row * LSDIM + col] : 0.0f;
        g_B[(size_t)row * KPAD + col] = __float2half_rn(v);
    }
}

// ---------------------------------------------------------------- K1: logsig
// dev[0] == 0, so only t=1,2 terms contribute to the Levy area:
//   levy(i,j) = d1h[i]*i1[j] - d1h[j]*i1[i] + d2h[i]*i2[j] - d2h[j]*i2[i]
// with d1h = 0.5(p1-p0), i1 = p2-p1, d2h = 0.5(p2-p0), i2 = p3-p2.
__global__ __launch_bounds__(256) void logsig_kernel(const float* __restrict__ x) {
    const int bs = blockIdx.x;           // 0..799
    const int b = bs / NSEG, s = bs % NSEG;
    const int tid = threadIdx.x;

    __shared__ float d1h[C][VV], i1[C][VV], d2h[C][VV], i2[C][VV];
    __shared__ float p0s[C][VV], lvs[C][VV];
    __shared__ uint8_t s_iu[LEVY], s_ju[LEVY];

    for (int idx = tid; idx < C * VV; idx += 256) {
        int c = idx / VV, v = idx % VV;
        const float* xb = x + (((size_t)b * C + c) * TT + s * SEGLEN) * VV + v;
        float x0 = xb[0], x1 = xb[VV], x2 = xb[2 * VV], x3 = xb[3 * VV];
        d1h[c][v] = 0.5f * (x1 - x0);
        i1 [c][v] = x2 - x1;
        d2h[c][v] = 0.5f * (x2 - x0);
        i2 [c][v] = x3 - x2;
        p0s[c][v] = x0;
        lvs[c][v] = x3 - x0;
    }
    for (int k = tid; k < LEVY; k += 256) {
        int i = 0, rem = k;
        while (rem >= (C - 1 - i)) { rem -= (C - 1 - i); i++; }
        s_iu[k] = (uint8_t)i;
        s_ju[k] = (uint8_t)(i + 1 + rem);
    }
    __syncthreads();

    for (int v = 0; v < VV; v++) {
        const size_t row = ((size_t)(b * VV + v) * NSEG + s);
        __half* oh = g_A + row * KPAD;

        for (int k = tid; k < LSDIM; k += 256) {
            float val;
            if (k < C) {
                val = lvs[k][v];
            } else if (k < C + LEVY) {
                int i = s_iu[k - C], j = s_ju[k - C];
                val = d1h[i][v] * i1[j][v] - d1h[j][v] * i1[i][v]
                    + d2h[i][v] * i2[j][v] - d2h[j][v] * i2[i][v];
            } else {
                val = p0s[k - C - LEVY][v];
            }
            oh[k] = __float2half_rn(val);
        }
    }
}

// ---------------------------------------------------------------- K2: fp16 mma GEMM
// CTA tile M=128 x N=128, BK=32 fp16, 8 warps (warp tile 64x32), 2-stage cp.async.
// Plain fp16 x fp16 -> f32:  ONE mma per fragment pair.
#define BKE       32                 // K elems per stage
#define SROW      40                 // smem row stride in fp16 elems (80 B)
#define ARR_BYTES (128 * SROW * 2)   // 10240 B per array
#define OFF_A     0
#define OFF_B     (ARR_BYTES)
#define STG       (2 * ARR_BYTES)    // 20480 B per stage
#define NSTAGE    2
#define GEMM_SMEM (NSTAGE * STG)     // 40960 B

extern __shared__ char dynsm[];

static __device__ __forceinline__ void load_stage(int tid, int bm, int bn, int s,
                                                  uint32_t sbase) {
    const size_t kb = (size_t)s * (BKE * 2);   // byte offset into a fp16 row
#pragma unroll
    for (int i = 0; i < 2; i++) {
        int ch  = tid + i * 256;     // 0..511 : 128 rows x 4 chunks(16B)
        int row = ch >> 2;
        int c   = ch & 3;
        uint32_t dst = (uint32_t)(row * (SROW * 2) + c * 16);
        size_t gA = (size_t)(bm + row) * ROWB + kb + c * 16;
        size_t gB = (size_t)(bn + row) * ROWB + kb + c * 16;
        cp16(sbase + OFF_A + dst, (const char*)g_A + gA);
        cp16(sbase + OFF_B + dst, (const char*)g_B + gB);
    }
    CP_COMMIT();
}

__global__ __launch_bounds__(256, 2) void gemm_mma_kernel() {
    __shared__ float s_bias[128];

    const int tid  = threadIdx.x;
    const int bn   = blockIdx.x * 128;   // N fastest: wave shares A tiles in L2
    const int bm   = blockIdx.y * 128;
    const int lane = tid & 31;
    const int wid  = tid >> 5;
    const int wm   = (wid >> 2) * 64;    // warp M origin (0 or 64)
    const int wn   = (wid & 3) * 32;     // warp N origin

    const uint32_t sbase = smem_u32(dynsm);

    if (tid < 128) s_bias[tid] = g_bias[bn + tid];

    // ldmatrix per-lane address components
    const int rowA = wm + (lane & 7) + (((lane >> 3) & 1) << 3);
    const int colA = ((lane >> 4) & 1) << 3;
    const int rowB = wn + (lane & 7) + (((lane >> 4) & 1) << 3);
    const int colB = ((lane >> 3) & 1) << 3;

    float acc[4][4][4];
#pragma unroll
    for (int f = 0; f < 4; f++)
#pragma unroll
        for (int n = 0; n < 4; n++)
#pragma unroll
            for (int q = 0; q < 4; q++) acc[f][n][q] = 0.0f;

    // prologue: stage 0
    load_stage(tid, bm, bn, 0, sbase);

    for (int s = 0; s < KSTAGES; s++) {
        CP_WAIT0();          // stage s is the only pending group -> resident
        __syncthreads();     // visibility + all warps done computing stage s-1

        if (s + 1 < KSTAGES) // prefetch next stage into the other buffer
            load_stage(tid, bm, bn, s + 1, sbase + (uint32_t)((s + 1) & 1) * STG);

        const uint32_t buf = sbase + (uint32_t)(s & 1) * STG;
#pragma unroll
        for (int kk = 0; kk < BKE; kk += 16) {
            uint32_t bfr[2][4];
#pragma unroll
            for (int p = 0; p < 2; p++) {
                uint32_t off = (uint32_t)(((rowB + 16 * p) * SROW + colB + kk) * 2);
                ldsm4(bfr[p], buf + OFF_B + off);
            }
#pragma unroll
            for (int f = 0; f < 4; f++) {
                uint32_t ah[4];
                uint32_t off = (uint32_t)(((rowA + 16 * f) * SROW + colA + kk) * 2);
                ldsm4(ah, buf + OFF_A + off);
#pragma unroll
                for (int n = 0; n < 4; n++)
                    mma16816(acc[f][n], ah, &bfr[n >> 1][(n & 1) * 2]);
            }
        }
    }

    // epilogue: acc rows r0 = base + lane/4, r1 = r0 + 8; cols 2*(lane%4)+{0,1}
    const int r0base = bm + wm + (lane >> 2);
    const int cloc   = wn + 2 * (lane & 3);
#pragma unroll
    for (int f = 0; f < 4; f++) {
        int r0 = r0base + f * 16;
        int r1 = r0 + 8;
#pragma unroll
        for (int n = 0; n < 4; n++) {
            int cl = cloc + n * 8;
            if (r0 < MROWS) {
                float2 v;
                v.x = acc[f][n][0] + s_bias[cl];
                v.y = acc[f][n][1] + s_bias[cl + 1];
                *(float2*)&g_xproj[(size_t)r0 * GATES + bn + cl] = v;
            }
            if (r1 < MROWS) {
                float2 v;
                v.x = acc[f][n][2] + s_bias[cl];
                v.y = acc[f][n][3] + s_bias[cl + 1];
                *(float2*)&g_xproj[(size_t)r1 * GATES + bn + cl] = v;
            }
        }
    }
}

// ---------------------------------------------------------------- K3: LSTM
// 134 blocks x 3 seqs, 512 threads (1 per gate col, 3 accumulators).
// W column split: k<96 in registers, k in [96,128) from dynamic smem.
// Next step's x_proj prefetched into registers before the k-loop.
#define SEQB  3
#define LBLK  134                 // ceil(400/3)
#define REGK  96
#define TAILK 32
#define LSTM_SMEM (TAILK * GATES * 4)

__global__ __launch_bounds__(512, 1) void lstm_kernel(float* __restrict__ out) {
    const int g = threadIdx.x;
    const int n0 = blockIdx.x * SEQB;

    __shared__ float4 hs[HID];        // x,y,z used for the 3 seqs
    __shared__ float  cs[SEQB][HID];
    __shared__ float  gsm[SEQB][GATES];
    float* sWtail = (float*)dynsm;    // [TAILK][GATES]

    float w[REGK];
#pragma unroll
    for (int k = 0; k < REGK; k++) w[k] = g_WhhT[k * GATES + g];
#pragma unroll
    for (int kk = 0; kk < TAILK; kk++)
        sWtail[kk * GATES + g] = g_WhhT[(REGK + kk) * GATES + g];

    if (g < HID) {
        hs[g] = make_float4(0.f, 0.f, 0.f, 0.f);
        cs[0][g] = 0.f; cs[1][g] = 0.f; cs[2][g] = 0.f;
    }
    __syncthreads();

    // clamped row pointers (invalid seqs read seq NSEQ-1 harmlessly)
    const int nc0 = (n0 + 0 < NSEQ) ? n0 + 0 : NSEQ - 1;
    const int nc1 = (n0 + 1 < NSEQ) ? n0 + 1 : NSEQ - 1;
    const int nc2 = (n0 + 2 < NSEQ) ? n0 + 2 : NSEQ - 1;
    const float* xp0 = g_xproj + (size_t)nc0 * NSEG * GATES + g;
    const float* xp1 = g_xproj + (size_t)nc1 * NSEG * GATES + g;
    const float* xp2 = g_xproj + (size_t)nc2 * NSEG * GATES + g;

    const int m_  = g >> 7;           // 0..3 ; update role only for m_ < 3
    const int hid = g & 127;
    const int n   = n0 + m_;
    const bool upd = (m_ < SEQB) && (n < NSEQ);
    float* outp = nullptr;
    if (upd) {
        const int b = n / VV, v = n % VV;
        outp = out + ((size_t)(b * HID + hid) * NSEG) * VV + v;
    }

    float a0 = xp0[0], a1 = xp1[0], a2 = xp2[0];

    for (int s = 0; s < NSEG; s++) {
        // prefetch next step (hidden behind the k-loop)
        float na0 = 0.f, na1 = 0.f, na2 = 0.f;
        if (s + 1 < NSEG) {
            na0 = xp0[(s + 1) * GATES];
            na1 = xp1[(s + 1) * GATES];
            na2 = xp2[(s + 1) * GATES];
        }
#pragma unroll
        for (int k = 0; k < REGK; k++) {
            float4 h4 = hs[k];
            float wk = w[k];
            a0 += h4.x * wk; a1 += h4.y * wk; a2 += h4.z * wk;
        }
#pragma unroll
        for (int kk = 0; kk < TAILK; kk++) {
            float4 h4 = hs[REGK + kk];
            float wk = sWtail[kk * GATES + g];
            a0 += h4.x * wk; a1 += h4.y * wk; a2 += h4.z * wk;
        }
        gsm[0][g] = a0; gsm[1][g] = a1; gsm[2][g] = a2;
        __syncthreads();

        if (upd) {
            float gi = gsm[m_][hid];
            float gf = gsm[m_][HID + hid];
            float gg = gsm[m_][2 * HID + hid];
            float go = gsm[m_][3 * HID + hid];
            float c  = cs[m_][hid];
            float cn = fast_sigmoid(gf) * c + fast_sigmoid(gi) * fast_tanh(gg);
            float h  = fast_sigmoid(go) * fast_tanh(cn);
            cs[m_][hid] = cn;
            ((float*)&hs[hid])[m_] = h;
            outp[s * VV] = h;
        }
        __syncthreads();

        a0 = na0; a1 = na1; a2 = na2;
    }
}

// ---------------------------------------------------------------- launch
extern "C" void kernel_launch(void* const* d_in, const int* in_sizes, int n_in,
                              void* d_out, int out_size) {
    const float* x   = (const float*)d_in[0];
    const float* Wih = (const float*)d_in[1];
    const float* Whh = (const float*)d_in[2];
    const float* bih = (const float*)d_in[3];
    const float* bhh = (const float*)d_in[4];
    float* out = (float*)d_out;

    cudaFuncSetAttribute(gemm_mma_kernel,
                         cudaFuncAttributeMaxDynamicSharedMemorySize, GEMM_SMEM);
    cudaFuncSetAttribute(lstm_kernel,
                         cudaFuncAttributeMaxDynamicSharedMemorySize, LSTM_SMEM);

    prep_kernel<<<HID, 512>>>(Whh, bih, bhh);
    wprep_kernel<<<GATES, 256>>>(Wih);
    logsig_kernel<<<16 * NSEG, 256>>>(x);
    dim3 grid(GATES / 128, MPAD / 128);   // (4, 157), N fastest
    gemm_mma_kernel<<<grid, 256, GEMM_SMEM>>>();
    lstm_kernel<<<LBLK, 512, LSTM_SMEM>>>(out);
}